// round 16
// baseline (speedup 1.0000x reference)
#include <cuda_runtime.h>

// DeepSets: out[s,f] = sx_s*W[0,f] + sy_s*W[1,f] + cnt_s*b[f]
// Linearity: segment_sum(xW+b) == segment_sum(x)@W + cnt*b.
//
// K1: warp-parallel 32-ary lower_bound per boundary -> g_offsets.
// K2: FOUR warps per segment (4096 CTAs x 128 thr = 16K warps -> warp-slot
//     cap 64/SM reached => ~128KB in flight/SM, vs 54KB at 1 warp/segment).
//     Each warp streams a quarter of the segment's float4 range with a
//     branch-free MLP-4 body (~1 iteration), smem combine of 4 partials,
//     warp 0 writes the 256B output row. Multi-wave grid keeps early rows'
//     C2C writes overlapped with later waves' HBM reads.

#define FEAT_OUT 64
#define NSEG_MAX 4096

__device__ int g_offsets[NSEG_MAX + 1];

__device__ __forceinline__ float warp_sum(float v)
{
    #pragma unroll
    for (int o = 16; o > 0; o >>= 1) v += __shfl_xor_sync(0xFFFFFFFFu, v, o);
    return v;
}

// ---------------------------------------------------------------------------
// K1: one warp per boundary target t in [0, num_segments].
// ---------------------------------------------------------------------------
__global__ __launch_bounds__(128)
void find_offsets_kernel(const int* __restrict__ ids, int N, int num_segments)
{
    const int lane   = threadIdx.x & 31;
    const int target = blockIdx.x * 4 + (threadIdx.x >> 5);
    if (target > num_segments) return;

    int lo = 0, hi = N;
    while (hi > lo) {
        const int m = hi - lo;
        const int p = lo + (int)(((long long)m * (lane + 1)) / 33);
        const int v = __ldg(&ids[p]);
        const unsigned pred = __ballot_sync(0xFFFFFFFFu, v < target);
        const int c = __popc(pred);
        int nlo, nhi;
        if (c == 0)  nlo = lo; else nlo = lo + (int)(((long long)m * c) / 33) + 1;
        if (c == 32) nhi = hi; else nhi = lo + (int)(((long long)m * (c + 1)) / 33);
        lo = nlo; hi = nhi;
    }
    if (lane == 0) g_offsets[target] = lo;
}

// ---------------------------------------------------------------------------
// K2: 4 warps per segment; branch-free MLP-4 body; smem combine.
// ---------------------------------------------------------------------------
__global__ __launch_bounds__(128)
void segment_kernel(const float4* __restrict__ xb,   // [N/2] point pairs
                    const float2* __restrict__ x2,   // [N] points
                    const float*  __restrict__ W,    // [2,64]
                    const float*  __restrict__ b,    // [64]
                    float*        __restrict__ out)  // [nseg,64]
{
    const int s    = blockIdx.x;
    const int t    = threadIdx.x;
    const int w    = t >> 5;     // warp 0..3
    const int lane = t & 31;

    const int start = __ldg(&g_offsets[s]);
    const int end   = __ldg(&g_offsets[s + 1]);

    float sx = 0.f, sy = 0.f;

    // Odd head/tail points: warp 0 lanes 0/1 (independent of the f4 stream).
    if (w == 0) {
        if (lane == 0 && (start & 1) && start < end) {
            const float2 p = __ldg(&x2[start]);
            sx += p.x; sy += p.y;
        }
        if (lane == 1 && (end & 1) && end > start) {
            const float2 p = __ldg(&x2[end - 1]);
            sx += p.x; sy += p.y;
        }
    }

    // Fully-interior float4 range [a0, a1), split 4 ways.
    const int a0   = (start + 1) >> 1;
    const int a1   = end >> 1;
    const int tot  = a1 - a0;                 // may be <= 0
    const int per  = (tot + 3) >> 2;
    const int wbeg = a0 + w * per;
    const int wend = min(wbeg + per, a1);

    // Branch-free MLP-4 body (typically exactly one iteration per warp).
    for (int j0 = wbeg + lane; j0 < wend; j0 += 128) {
        const int j1 = j0 + 32, j2 = j0 + 64, j3 = j0 + 96;
        const float4 v0 = __ldg(&xb[j0]);                 // j0 < wend
        const float4 v1 = __ldg(&xb[min(j1, wend - 1)]);  // wend-1 >= wbeg >= a0
        const float4 v2 = __ldg(&xb[min(j2, wend - 1)]);
        const float4 v3 = __ldg(&xb[min(j3, wend - 1)]);
        const float m1 = (j1 < wend) ? 1.f : 0.f;
        const float m2 = (j2 < wend) ? 1.f : 0.f;
        const float m3 = (j3 < wend) ? 1.f : 0.f;
        sx += (v0.x + v0.z) + m1 * (v1.x + v1.z)
            + m2 * (v2.x + v2.z) + m3 * (v3.x + v3.z);
        sy += (v0.y + v0.w) + m1 * (v1.y + v1.w)
            + m2 * (v2.y + v2.w) + m3 * (v3.y + v3.w);
    }

    sx = warp_sum(sx);
    sy = warp_sum(sy);

    __shared__ float wsx[4], wsy[4];
    if (lane == 0) { wsx[w] = sx; wsy[w] = sy; }
    __syncthreads();

    if (t < 16) {
        const float SX = wsx[0] + wsx[1] + wsx[2] + wsx[3];
        const float SY = wsy[0] + wsy[1] + wsy[2] + wsy[3];
        const float4 w0 = __ldg((const float4*)W + t);
        const float4 w1 = __ldg((const float4*)W + 16 + t);
        const float4 bb = __ldg((const float4*)b + t);
        const float cnt = (float)(end - start);
        float4 o;
        o.x = fmaf(SX, w0.x, fmaf(SY, w1.x, cnt * bb.x));
        o.y = fmaf(SX, w0.y, fmaf(SY, w1.y, cnt * bb.y));
        o.z = fmaf(SX, w0.z, fmaf(SY, w1.z, cnt * bb.z));
        o.w = fmaf(SX, w0.w, fmaf(SY, w1.w, cnt * bb.w));
        reinterpret_cast<float4*>(out)[s * 16 + t] = o;
    }
}

extern "C" void kernel_launch(void* const* d_in, const int* in_sizes, int n_in,
                              void* d_out, int out_size)
{
    const float* xf  = (const float*)d_in[0];    // [N,2]
    const int*   ids = (const int*)d_in[1];      // [N] sorted
    const float* W   = (const float*)d_in[2];    // [2,64]
    const float* b   = (const float*)d_in[3];    // [64]
    float* out = (float*)d_out;

    const int N = in_sizes[0] / 2;
    const int num_segments = out_size / FEAT_OUT;   // 4096

    const int nb1 = (num_segments + 1 + 3) / 4;
    find_offsets_kernel<<<nb1, 128>>>(ids, N, num_segments);

    segment_kernel<<<num_segments, 128>>>((const float4*)xf, (const float2*)xf,
                                          W, b, out);
}

// round 17
// speedup vs baseline: 1.0200x; 1.0200x over previous
#include <cuda_runtime.h>

// DeepSets: out[s,f] = sx_s*W[0,f] + sy_s*W[1,f] + cnt_s*b[f]
// Linearity: segment_sum(xW+b) == segment_sum(x)@W + cnt*b.
//
// K1: warp-parallel 32-ary lower_bound per boundary -> g_offsets.
// K2: TWO warps per segment (4096 CTAs x 64 thr = 8192 warps = 54/SM, near
//     the warp-slot cap; ~108KB in flight/SM vs 54KB at 1 warp/segment).
//     Per-warp range ~119 float4 = exactly one branch-free MLP-4 iteration
//     (no wasted masked slots, unlike the 4-way split). Minimal combine:
//     one 2-element smem exchange. Multi-wave grid keeps early rows' output
//     writes overlapped with later waves' reads.

#define FEAT_OUT 64
#define NSEG_MAX 4096

__device__ int g_offsets[NSEG_MAX + 1];

__device__ __forceinline__ float warp_sum(float v)
{
    #pragma unroll
    for (int o = 16; o > 0; o >>= 1) v += __shfl_xor_sync(0xFFFFFFFFu, v, o);
    return v;
}

// ---------------------------------------------------------------------------
// K1: one warp per boundary target t in [0, num_segments].
// ---------------------------------------------------------------------------
__global__ __launch_bounds__(128)
void find_offsets_kernel(const int* __restrict__ ids, int N, int num_segments)
{
    const int lane   = threadIdx.x & 31;
    const int target = blockIdx.x * 4 + (threadIdx.x >> 5);
    if (target > num_segments) return;

    int lo = 0, hi = N;
    while (hi > lo) {
        const int m = hi - lo;
        const int p = lo + (int)(((long long)m * (lane + 1)) / 33);
        const int v = __ldg(&ids[p]);
        const unsigned pred = __ballot_sync(0xFFFFFFFFu, v < target);
        const int c = __popc(pred);
        int nlo, nhi;
        if (c == 0)  nlo = lo; else nlo = lo + (int)(((long long)m * c) / 33) + 1;
        if (c == 32) nhi = hi; else nhi = lo + (int)(((long long)m * (c + 1)) / 33);
        lo = nlo; hi = nhi;
    }
    if (lane == 0) g_offsets[target] = lo;
}

// ---------------------------------------------------------------------------
// K2: 2 warps per segment; branch-free MLP-4 body; 2-element smem combine.
// ---------------------------------------------------------------------------
__global__ __launch_bounds__(64)
void segment_kernel(const float4* __restrict__ xb,   // [N/2] point pairs
                    const float2* __restrict__ x2,   // [N] points
                    const float*  __restrict__ W,    // [2,64]
                    const float*  __restrict__ b,    // [64]
                    float*        __restrict__ out)  // [nseg,64]
{
    const int s    = blockIdx.x;
    const int t    = threadIdx.x;
    const int w    = t >> 5;     // warp 0..1
    const int lane = t & 31;

    const int start = __ldg(&g_offsets[s]);
    const int end   = __ldg(&g_offsets[s + 1]);

    float sx = 0.f, sy = 0.f;

    // Odd head/tail points: warp 0 lane 0, warp 1 lane 0 (parallel, cheap).
    if (lane == 0) {
        if (w == 0 && (start & 1) && start < end) {
            const float2 p = __ldg(&x2[start]);
            sx += p.x; sy += p.y;
        }
        if (w == 1 && (end & 1) && end > start) {
            const float2 p = __ldg(&x2[end - 1]);
            sx += p.x; sy += p.y;
        }
    }

    // Fully-interior float4 range [a0, a1), split in halves.
    const int a0   = (start + 1) >> 1;
    const int a1   = end >> 1;
    const int tot  = a1 - a0;                 // may be <= 0
    const int per  = (tot + 1) >> 1;
    const int wbeg = a0 + w * per;
    const int wend = min(wbeg + per, a1);

    // Branch-free MLP-4 body (typically exactly one iteration per warp).
    for (int j0 = wbeg + lane; j0 < wend; j0 += 128) {
        const int j1 = j0 + 32, j2 = j0 + 64, j3 = j0 + 96;
        const float4 v0 = __ldg(&xb[j0]);                 // j0 < wend
        const float4 v1 = __ldg(&xb[min(j1, wend - 1)]);  // wend-1 >= a0 >= 0
        const float4 v2 = __ldg(&xb[min(j2, wend - 1)]);
        const float4 v3 = __ldg(&xb[min(j3, wend - 1)]);
        const float m1 = (j1 < wend) ? 1.f : 0.f;
        const float m2 = (j2 < wend) ? 1.f : 0.f;
        const float m3 = (j3 < wend) ? 1.f : 0.f;
        sx += (v0.x + v0.z) + m1 * (v1.x + v1.z)
            + m2 * (v2.x + v2.z) + m3 * (v3.x + v3.z);
        sy += (v0.y + v0.w) + m1 * (v1.y + v1.w)
            + m2 * (v2.y + v2.w) + m3 * (v3.y + v3.w);
    }

    sx = warp_sum(sx);
    sy = warp_sum(sy);

    __shared__ float wsx[2], wsy[2];
    if (lane == 0) { wsx[w] = sx; wsy[w] = sy; }
    __syncthreads();

    if (t < 16) {
        const float SX = wsx[0] + wsx[1];
        const float SY = wsy[0] + wsy[1];
        const float4 w0 = __ldg((const float4*)W + t);
        const float4 w1 = __ldg((const float4*)W + 16 + t);
        const float4 bb = __ldg((const float4*)b + t);
        const float cnt = (float)(end - start);
        float4 o;
        o.x = fmaf(SX, w0.x, fmaf(SY, w1.x, cnt * bb.x));
        o.y = fmaf(SX, w0.y, fmaf(SY, w1.y, cnt * bb.y));
        o.z = fmaf(SX, w0.z, fmaf(SY, w1.z, cnt * bb.z));
        o.w = fmaf(SX, w0.w, fmaf(SY, w1.w, cnt * bb.w));
        reinterpret_cast<float4*>(out)[s * 16 + t] = o;
    }
}

extern "C" void kernel_launch(void* const* d_in, const int* in_sizes, int n_in,
                              void* d_out, int out_size)
{
    const float* xf  = (const float*)d_in[0];    // [N,2]
    const int*   ids = (const int*)d_in[1];      // [N] sorted
    const float* W   = (const float*)d_in[2];    // [2,64]
    const float* b   = (const float*)d_in[3];    // [64]
    float* out = (float*)d_out;

    const int N = in_sizes[0] / 2;
    const int num_segments = out_size / FEAT_OUT;   // 4096

    const int nb1 = (num_segments + 1 + 3) / 4;
    find_offsets_kernel<<<nb1, 128>>>(ids, N, num_segments);

    segment_kernel<<<num_segments, 64>>>((const float4*)xf, (const float2*)xf,
                                         W, b, out);
}